// round 1
// baseline (speedup 1.0000x reference)
#include <cuda_runtime.h>
#include <math.h>

#define T_LEN   3000
#define C_CH    1024
#define KSIZE   24
#define THREADS 256
#define ROUT    12          // outputs per thread; 250 active threads cover 3000
#define HALO    (KSIZE - 1) // 23

// Shared row buffer: [0..22] zero halo, [23..3022] data, pad to allow the last
// thread's float4 window read (reads up to s[3023], value unused).
#define SBUF_LEN (HALO + T_LEN + 17)   // 3040 floats = 12160 B

__global__ __launch_bounds__(THREADS, 2)
void ssm4d_conv_kernel(const float* __restrict__ x,
                       const float* __restrict__ alpha,
                       const float* __restrict__ beta,
                       const float* __restrict__ theta,
                       float* __restrict__ y)
{
    __shared__ __align__(16) float s[SBUF_LEN];
    __shared__ float wsh[KSIZE];

    const int row = blockIdx.x;            // row = b*C + c
    const int c   = row & (C_CH - 1);
    const float* __restrict__ xr = x + (size_t)row * T_LEN;
    float* __restrict__       yr = y + (size_t)row * T_LEN;
    const int tid = threadIdx.x;

    // Zero the causal halo (and the small tail pad, cheap + deterministic).
    if (tid < HALO) s[tid] = 0.0f;
    if (tid >= HALO && tid < HALO + 17) s[T_LEN + tid] = 0.0f;

    // Synthesize the 24 depthwise taps for this channel (once per block).
    // Matches reference exactly: w[k] = beta * exp(log(max(alpha,1e-6))*k) *
    //                                   (1 - (theta*k)^2/2 + (theta*k)^4/24)
    if (tid < KSIZE) {
        float a   = fmaxf(alpha[c], 1e-6f);
        float la  = logf(a);
        float k   = (float)tid;
        float dec = expf(la * k);
        float xx  = theta[c] * k;
        float x2  = xx * xx;
        float ph  = 1.0f - 0.5f * x2 + (x2 * x2) * (1.0f / 24.0f);
        wsh[tid]  = beta[c] * dec * ph;
    }

    // Stage the row into shared memory, coalesced.
    #pragma unroll
    for (int i = tid; i < T_LEN; i += THREADS)
        s[HALO + i] = xr[i];

    __syncthreads();

    if (tid < T_LEN / ROUT) {   // 250 active threads
        // Weights into registers (LDS broadcast, conflict-free).
        float w[KSIZE];
        #pragma unroll
        for (int k = 0; k < KSIZE; k++) w[k] = wsh[k];

        const int t0 = tid * ROUT;          // 48B-aligned window start

        // Register sliding window: 36 floats via 9 LDS.128 (only [0..34] used).
        float xw[36];
        #pragma unroll
        for (int i = 0; i < 36; i += 4) {
            float4 v = *reinterpret_cast<const float4*>(&s[t0 + i]);
            xw[i]   = v.x; xw[i+1] = v.y; xw[i+2] = v.z; xw[i+3] = v.w;
        }

        float acc[ROUT];
        #pragma unroll
        for (int r = 0; r < ROUT; r++) acc[r] = 0.0f;

        // y[t0+r] = sum_k w[k] * x[t0+r+k-23]  ==  sum_k w[k] * s[t0+r+k]
        #pragma unroll
        for (int k = 0; k < KSIZE; k++) {
            #pragma unroll
            for (int r = 0; r < ROUT; r++)
                acc[r] = fmaf(w[k], xw[r + k], acc[r]);
        }

        // Vectorized store: 3x STG.128 per thread.
        #pragma unroll
        for (int r = 0; r < ROUT; r += 4) {
            float4 v = make_float4(acc[r], acc[r+1], acc[r+2], acc[r+3]);
            *reinterpret_cast<float4*>(&yr[t0 + r]) = v;
        }
    }
}

extern "C" void kernel_launch(void* const* d_in, const int* in_sizes, int n_in,
                              void* d_out, int out_size)
{
    const float* x     = (const float*)d_in[0];
    const float* alpha = (const float*)d_in[1];
    const float* beta  = (const float*)d_in[2];
    const float* theta = (const float*)d_in[3];
    float* y = (float*)d_out;

    const int rows = in_sizes[0] / T_LEN;   // B*C = 16384
    ssm4d_conv_kernel<<<rows, THREADS>>>(x, alpha, beta, theta, y);
}